// round 10
// baseline (speedup 1.0000x reference)
#include <cuda_runtime.h>
#include <cuda_bf16.h>
#include <cuda_fp16.h>
#include <cstdint>

// EdgePredictor, factorized:
//   Stage 1: fp16 1-pass GEMM  Y[100000,256] = X@W  (fp32 acc). Convert of the
//            NEXT tile is interleaved into the MMA k-loop (double-buffered AH);
//            one syncthreads per tile; cp.async chunks are thread-private.
//            A = Y[:,:128]+b1, B = Y[:,128:] stored fp16.
//   Stage 2: out[e] = relu(A[row] + B[col]) @ W2 + b2, 8 lanes/edge:
//            each warp LDG.128 covers 4 edges x 128B = 4 full L1 lines (floor).

#define ND  128
#define MAX_NODES 100000
#define TILE_M 128

__device__ __half g_Ah[(size_t)MAX_NODES * ND];   // 25.6 MB
__device__ __half g_Bh[(size_t)MAX_NODES * ND];   // 25.6 MB

// SMEM layout (dynamic, 192.5 KB)
#define SM_W    0          // 65536  W' fp16 [n=256][k=128], 256B rows, swizzled
#define SM_ARAW 65536      // 65536  raw fp32 X tile (128 x 128 f32)
#define SM_AH0  131072     // 32768  fp16 X tile buf 0 (swizzled)
#define SM_AH1  163840     // 32768  fp16 X tile buf 1
#define SM_B1   196608     // 512
#define SMEM_TOTAL 197120

// XOR swizzle for 256-byte rows: byte bits [4:6] ^= row bits [8:10]
#define SWZ(x) ((x) ^ (((x) >> 4) & 0x70))

static __device__ __forceinline__ uint32_t smem_u32(const void* p) {
    uint32_t a;
    asm("{ .reg .u64 t; cvta.to.shared.u64 t, %1; cvt.u32.u64 %0, t; }" : "=r"(a) : "l"(p));
    return a;
}

#define LDSM4(r, addr)                                                          \
    asm volatile("ldmatrix.sync.aligned.m8n8.x4.shared.b16 {%0,%1,%2,%3}, [%4];"\
        : "=r"((r)[0]), "=r"((r)[1]), "=r"((r)[2]), "=r"((r)[3]) : "r"(addr))

#define MMA16816F(d, a, b)                                                      \
    asm volatile("mma.sync.aligned.m16n8k16.row.col.f32.f16.f16.f32 "           \
        "{%0,%1,%2,%3}, {%4,%5,%6,%7}, {%8,%9}, {%0,%1,%2,%3};"                 \
        : "+f"((d)[0]), "+f"((d)[1]), "+f"((d)[2]), "+f"((d)[3])                \
        : "r"((a)[0]), "r"((a)[1]), "r"((a)[2]), "r"((a)[3]),                   \
          "r"((b)[0]), "r"((b)[1]))

#define CP_ASYNC16(dst, src, nbytes)                                            \
    asm volatile("cp.async.cg.shared.global [%0], [%1], 16, %2;"                \
        :: "r"(dst), "l"(src), "r"(nbytes))
#define CP_COMMIT() asm volatile("cp.async.commit_group;" ::: "memory")
#define CP_WAIT0()  asm volatile("cp.async.wait_group 0;" ::: "memory")

// ---------------------------------------------------------------------------
// Stage 1: persistent pipelined fp16 GEMM. 512 threads, 16 warps (4m x 4n),
// CTA tile 128x256, warp tile 32x64, convert-of-next-tile fused into MMA loop.
// ---------------------------------------------------------------------------
__global__ __launch_bounds__(512, 1) void gemm_kernel(
    const float* __restrict__ x, const float* __restrict__ W1,
    const float* __restrict__ b1, int nnodes, int ntiles)
{
    extern __shared__ char smem[];
    const uint32_t sb = smem_u32(smem);
    const int tid  = threadIdx.x;
    const int lane = tid & 31;
    const int w    = tid >> 5;
    const int warp_m = w & 3;    // 4 groups of 32 rows
    const int warp_n = w >> 2;   // 4 groups of 64 cols

    // staging coords: 4096 float4 / 512 threads = 8 each (thread-private chunks)
    const int prow = tid >> 5;          // + it*16
    const int pc4  = tid & 31;

    // ---- prefetch first raw tile ----
    int tile = blockIdx.x;
    {
        long base = (long)tile * TILE_M;
        #pragma unroll
        for (int it = 0; it < 8; it++) {
            int row = prow + it * 16;
            long node = base + row;
            const char* src = (const char*)(x + node * (long)ND) + pc4 * 16;
            uint32_t dst = sb + SM_ARAW + row * 512 + pc4 * 16;
            int nb = (tile < ntiles && node < nnodes) ? 16 : 0;
            if (nb == 0) src = (const char*)x;
            CP_ASYNC16(dst, src, nb);
        }
        CP_COMMIT();
    }

    // ---- build W' fp16 image while first tile loads ----
    // W'[n][k]: n<128 -> W1[k][n] ; n>=128 -> W1[128+k][n-128]
    #pragma unroll
    for (int i = tid; i < 256 * 128; i += 512) {
        int r = i >> 7, c = i & 127;
        int k = (r < 128) ? r : (r - 128);
        int n = (r < 128) ? c : (c + 128);
        __half hv = __float2half_rn(W1[i]);
        *(__half*)(smem + SM_W + SWZ((uint32_t)(n * 256 + k * 2))) = hv;
    }
    if (tid < 128) ((float*)(smem + SM_B1))[tid] = b1[tid];

    // ---- convert first tile -> AH0 (thread-private ARAW chunks: no sync) ----
    CP_WAIT0();
    #pragma unroll
    for (int it = 0; it < 8; it++) {
        int row = prow + it * 16;
        float4 v = *(const float4*)(smem + SM_ARAW + row * 512 + pc4 * 16);
        __half2 h01 = __floats2half2_rn(v.x, v.y);
        __half2 h23 = __floats2half2_rn(v.z, v.w);
        uint2 hp; hp.x = *(uint32_t*)&h01; hp.y = *(uint32_t*)&h23;
        *(uint2*)(smem + SM_AH0 + SWZ((uint32_t)(row * 256 + pc4 * 8))) = hp;
    }
    // ---- issue cp.async for tile+grid ----
    {
        int nxt = tile + gridDim.x;
        long nbase = (long)nxt * TILE_M;
        #pragma unroll
        for (int it = 0; it < 8; it++) {
            int row = prow + it * 16;
            long node = nbase + row;
            const char* src = (const char*)(x + node * (long)ND) + pc4 * 16;
            uint32_t dst = sb + SM_ARAW + row * 512 + pc4 * 16;
            int nb = (nxt < ntiles && node < nnodes) ? 16 : 0;
            if (nb == 0) src = (const char*)x;
            CP_ASYNC16(dst, src, nb);
        }
        CP_COMMIT();
    }
    __syncthreads();   // AH0 visible to all warps

    // ldmatrix lane address components
    const int a_row = (lane & 15);
    const int a_ko  = (lane >> 4) << 4;
    const int b_row = (lane & 7) + ((lane >> 4) << 3);
    const int b_ko  = ((lane >> 3) & 1) << 4;

    int cur = 0;
    for (; tile < ntiles; tile += gridDim.x) {
        const long base = (long)tile * TILE_M;
        const uint32_t ahc = sb + (cur ? SM_AH1 : SM_AH0);
        const uint32_t ahn = sb + (cur ? SM_AH0 : SM_AH1);

        CP_WAIT0();   // raw(tile+grid) landed (thread-private chunks)

        // ---- fused MMA + convert-next loop ----
        float acc[2][8][4];
        #pragma unroll
        for (int ms = 0; ms < 2; ms++)
            #pragma unroll
            for (int ns = 0; ns < 8; ns++)
                #pragma unroll
                for (int e = 0; e < 4; e++) acc[ms][ns][e] = 0.f;

        #pragma unroll
        for (int ks = 0; ks < 8; ks++) {
            // convert one chunk of next tile (ALU/LSU, overlaps tensor pipe)
            {
                int row = prow + ks * 16;
                float4 v = *(const float4*)(smem + SM_ARAW + row * 512 + pc4 * 16);
                __half2 h01 = __floats2half2_rn(v.x, v.y);
                __half2 h23 = __floats2half2_rn(v.z, v.w);
                uint2 hp; hp.x = *(uint32_t*)&h01; hp.y = *(uint32_t*)&h23;
                *(uint2*)(ahn - sb + smem + SWZ((uint32_t)(row * 256 + pc4 * 8))) = hp;
            }
            uint32_t av[2][4], bv[16];
            #pragma unroll
            for (int ms = 0; ms < 2; ms++) {
                uint32_t ab = SWZ((uint32_t)((warp_m * 32 + ms * 16 + a_row) * 256
                                             + ks * 32 + a_ko));
                LDSM4(av[ms], ahc + ab);
            }
            #pragma unroll
            for (int bj = 0; bj < 4; bj++) {
                uint32_t bb = SWZ((uint32_t)((warp_n * 64 + bj * 16 + b_row) * 256
                                             + ks * 32 + b_ko));
                LDSM4(&bv[bj * 4], sb + SM_W + bb);
            }
            #pragma unroll
            for (int ms = 0; ms < 2; ms++)
                #pragma unroll
                for (int ns = 0; ns < 8; ns++)
                    MMA16816F(acc[ms][ns], av[ms], &bv[ns * 2]);
        }

        // ---- epilogue: fp16 stores ----
        __half* dsth = (warp_n < 2) ? g_Ah : g_Bh;
        const int colbase = (warp_n & 1) * 64 + 2 * (lane & 3);
        const int rowbase = warp_m * 32 + (lane >> 2);
        const float* b1s = (const float*)(smem + SM_B1);

        #pragma unroll
        for (int ms = 0; ms < 2; ms++) {
            #pragma unroll
            for (int ns = 0; ns < 8; ns++) {
                const int col = colbase + ns * 8;
                float bias0 = 0.f, bias1 = 0.f;
                if (warp_n < 2) { bias0 = b1s[col]; bias1 = b1s[col + 1]; }
                long node0 = base + rowbase + ms * 16;
                if (node0 < nnodes)
                    *(__half2*)(dsth + node0 * (long)ND + col) =
                        __floats2half2_rn(acc[ms][ns][0] + bias0, acc[ms][ns][1] + bias1);
                long node1 = node0 + 8;
                if (node1 < nnodes)
                    *(__half2*)(dsth + node1 * (long)ND + col) =
                        __floats2half2_rn(acc[ms][ns][2] + bias0, acc[ms][ns][3] + bias1);
            }
        }

        __syncthreads();   // AH[nxt] writes visible; AH[cur] reads complete

        // ---- issue cp.async for tile+2*grid into ARAW ----
        {
            int nxt = tile + 2 * gridDim.x;
            long nbase = (long)nxt * TILE_M;
            #pragma unroll
            for (int it = 0; it < 8; it++) {
                int row = prow + it * 16;
                long node = nbase + row;
                const char* src = (const char*)(x + node * (long)ND) + pc4 * 16;
                uint32_t dst = sb + SM_ARAW + row * 512 + pc4 * 16;
                int nb = (nxt < ntiles && node < nnodes) ? 16 : 0;
                if (nb == 0) src = (const char*)x;
                CP_ASYNC16(dst, src, nb);
            }
            CP_COMMIT();
        }
        cur ^= 1;
    }
}

// ---------------------------------------------------------------------------
// Stage 2: 8 lanes/edge, 4 edges/warp. Lane t reads uint4 chunks t and t+8 of
// each 256B row -> every warp LDG.128 covers 4 edges x 128 contiguous bytes
// = 4 full L1 lines (wavefront floor). 3-level shuffle reduce.
// ---------------------------------------------------------------------------
__global__ __launch_bounds__(256) void edge_kernel(
    const int* __restrict__ ei,        // [2, E] int32
    const float* __restrict__ W2,      // [128, 2]
    const float* __restrict__ b2,      // [2]
    float* __restrict__ out,           // [E, 2]
    int E)
{
    __shared__ float w2a[ND];
    __shared__ float w2b[ND];
    const int tid = threadIdx.x;
    if (tid < ND) {
        w2a[tid] = W2[tid * 2 + 0];
        w2b[tid] = W2[tid * 2 + 1];
    }
    __syncthreads();

    const int lane = tid & 31;
    const int t    = lane & 7;        // chunk within row (0..7)
    const int sub  = lane >> 3;       // edge within warp (0..3)
    const float b20 = __ldg(b2), b21 = __ldg(b2 + 1);
    const __half2 z2 = __float2half2_rn(0.f);

    const int warp   = (blockIdx.x * blockDim.x + tid) >> 5;
    const int nwarps = (gridDim.x * blockDim.x) >> 5;

    const float4* wa4 = (const float4*)w2a;   // 32 float4 (k-chunks of 4)
    const float4* wb4 = (const float4*)w2b;

    for (int eb = warp * 4; eb < E; eb += nwarps * 4) {
        const int e = eb + sub;       // E % 4 == 0
        const int r = __ldg(ei + e);
        const int c = __ldg(ei + (size_t)E + e);

        const uint4* pa = (const uint4*)(g_Ah + (size_t)r * ND);  // 16 chunks
        const uint4* pb = (const uint4*)(g_Bh + (size_t)c * ND);

        // chunk t (k = t*8..t*8+7) and chunk t+8 (k = 64+t*8 ..)
        uint4 a0 = __ldg(pa + t);
        uint4 b0 = __ldg(pb + t);
        uint4 a1 = __ldg(pa + t + 8);
        uint4 b1v = __ldg(pb + t + 8);

        float o0 = 0.f, o1 = 0.f;
        #pragma unroll
        for (int half = 0; half < 2; half++) {
            const uint4 a4 = half ? a1 : a0;
            const uint4 b4 = half ? b1v : b0;
            const int ch = t + half * 8;
            const float4 wal = wa4[ch * 2], wah = wa4[ch * 2 + 1];
            const float4 wbl = wb4[ch * 2], wbh = wb4[ch * 2 + 1];

            const __half2* ap = (const __half2*)&a4;
            const __half2* bp = (const __half2*)&b4;

            float2 f0 = __half22float2(__hmax2(__hadd2(ap[0], bp[0]), z2));
            float2 f1 = __half22float2(__hmax2(__hadd2(ap[1], bp[1]), z2));
            float2 f2 = __half22float2(__hmax2(__hadd2(ap[2], bp[2]), z2));
            float2 f3 = __half22float2(__hmax2(__hadd2(ap[3], bp[3]), z2));

            o0 = fmaf(f0.x, wal.x, fmaf(f0.y, wal.y, o0));
            o0 = fmaf(f1.x, wal.z, fmaf(f1.y, wal.w, o0));
            o0 = fmaf(f2.x, wah.x, fmaf(f2.y, wah.y, o0));
            o0 = fmaf(f3.x, wah.z, fmaf(f3.y, wah.w, o0));

            o1 = fmaf(f0.x, wbl.x, fmaf(f0.y, wbl.y, o1));
            o1 = fmaf(f1.x, wbl.z, fmaf(f1.y, wbl.w, o1));
            o1 = fmaf(f2.x, wbh.x, fmaf(f2.y, wbh.y, o1));
            o1 = fmaf(f3.x, wbh.z, fmaf(f3.y, wbh.w, o1));
        }

        o0 += __shfl_xor_sync(0xFFFFFFFFu, o0, 1);
        o0 += __shfl_xor_sync(0xFFFFFFFFu, o0, 2);
        o0 += __shfl_xor_sync(0xFFFFFFFFu, o0, 4);
        o1 += __shfl_xor_sync(0xFFFFFFFFu, o1, 1);
        o1 += __shfl_xor_sync(0xFFFFFFFFu, o1, 2);
        o1 += __shfl_xor_sync(0xFFFFFFFFu, o1, 4);

        if (t == 0) {
            *(float2*)(out + 2 * (size_t)e) = make_float2(o0 + b20, o1 + b21);
        }
    }
}

// ---------------------------------------------------------------------------
extern "C" void kernel_launch(void* const* d_in, const int* in_sizes, int n_in,
                              void* d_out, int out_size)
{
    const float* x  = (const float*)d_in[0];      // [N,128]
    const int*   ei = (const int*)d_in[1];        // [2,E] int32
    const float* W1 = (const float*)d_in[2];      // [256,128]
    const float* b1 = (const float*)d_in[3];      // [128]
    const float* W2 = (const float*)d_in[4];      // [128,2]
    const float* b2 = (const float*)d_in[5];      // [2]
    float*       out = (float*)d_out;             // [E,2]

    const int nnodes = in_sizes[0] / ND;
    const int E      = in_sizes[1] / 2;
    const int ntiles = (nnodes + TILE_M - 1) / TILE_M;

    cudaFuncSetAttribute(gemm_kernel, cudaFuncAttributeMaxDynamicSharedMemorySize,
                         SMEM_TOTAL);

    gemm_kernel<<<148, 512, SMEM_TOTAL>>>(x, W1, b1, nnodes, ntiles);
    edge_kernel<<<(E + 31) / 32, 256>>>(ei, W2, b2, out, E);
}

// round 11
// speedup vs baseline: 1.1683x; 1.1683x over previous
#include <cuda_runtime.h>
#include <cuda_bf16.h>
#include <cuda_fp16.h>
#include <cstdint>

// EdgePredictor, factorized:
//   Stage 1: fp16 1-pass GEMM  Y[100000,256] = X@W  (fp32 acc). 256-thread CTAs,
//            tile 64x256, 112.8KB smem -> 2 CTAs/SM co-resident: one CTA's MMAs
//            cover the other's convert/barrier stalls.
//            A = Y[:,:128]+b1, B = Y[:,128:] stored fp16.
//   Stage 2: out[e] = relu(A[row] + B[col]) @ W2 + b2  (round-9 proven config:
//            4 lanes/edge, 8 edges/warp, 64B/instr, MLP=8).

#define ND  128
#define MAX_NODES 100000
#define TILE_M 64

__device__ __half g_Ah[(size_t)MAX_NODES * ND];   // 25.6 MB
__device__ __half g_Bh[(size_t)MAX_NODES * ND];   // 25.6 MB

// SMEM layout (dynamic, 112.8 KB per CTA)
#define SM_W    0          // 65536  W' fp16 [n=256][k=128], 256B rows, swizzled
#define SM_ARAW 65536      // 32768  raw fp32 X tile (64 x 128 f32)
#define SM_AH   98304      // 16384  fp16 X tile (64 x 128), swizzled
#define SM_B1   114688     // 512
#define SMEM_TOTAL 115200

// XOR swizzle for 256-byte rows: byte bits [4:6] ^= row bits [8:10]
#define SWZ(x) ((x) ^ (((x) >> 4) & 0x70))

static __device__ __forceinline__ uint32_t smem_u32(const void* p) {
    uint32_t a;
    asm("{ .reg .u64 t; cvta.to.shared.u64 t, %1; cvt.u32.u64 %0, t; }" : "=r"(a) : "l"(p));
    return a;
}

#define LDSM4(r, addr)                                                          \
    asm volatile("ldmatrix.sync.aligned.m8n8.x4.shared.b16 {%0,%1,%2,%3}, [%4];"\
        : "=r"((r)[0]), "=r"((r)[1]), "=r"((r)[2]), "=r"((r)[3]) : "r"(addr))

#define MMA16816F(d, a, b)                                                      \
    asm volatile("mma.sync.aligned.m16n8k16.row.col.f32.f16.f16.f32 "           \
        "{%0,%1,%2,%3}, {%4,%5,%6,%7}, {%8,%9}, {%0,%1,%2,%3};"                 \
        : "+f"((d)[0]), "+f"((d)[1]), "+f"((d)[2]), "+f"((d)[3])                \
        : "r"((a)[0]), "r"((a)[1]), "r"((a)[2]), "r"((a)[3]),                   \
          "r"((b)[0]), "r"((b)[1]))

#define CP_ASYNC16(dst, src, nbytes)                                            \
    asm volatile("cp.async.cg.shared.global [%0], [%1], 16, %2;"                \
        :: "r"(dst), "l"(src), "r"(nbytes))
#define CP_COMMIT() asm volatile("cp.async.commit_group;" ::: "memory")
#define CP_WAIT0()  asm volatile("cp.async.wait_group 0;" ::: "memory")

// ---------------------------------------------------------------------------
// Stage 1: persistent pipelined fp16 GEMM. 256 threads, 8 warps (2m x 4n),
// CTA tile 64x256, warp tile 32x64, 2 CTAs/SM.
// ---------------------------------------------------------------------------
__global__ __launch_bounds__(256, 2) void gemm_kernel(
    const float* __restrict__ x, const float* __restrict__ W1,
    const float* __restrict__ b1, int nnodes, int ntiles)
{
    extern __shared__ char smem[];
    const uint32_t sb = smem_u32(smem);
    const int tid  = threadIdx.x;
    const int lane = tid & 31;
    const int w    = tid >> 5;
    const int warp_m = w & 1;    // 2 groups of 32 rows
    const int warp_n = w >> 1;   // 4 groups of 64 cols

    // staging coords: 2048 float4 per tile / 256 threads = 8 each (thread-private)
    const int prow = tid >> 5;          // + it*8
    const int pc4  = tid & 31;

    // ---- prefetch first raw tile ----
    int tile = blockIdx.x;
    {
        long base = (long)tile * TILE_M;
        #pragma unroll
        for (int it = 0; it < 8; it++) {
            int row = prow + it * 8;
            long node = base + row;
            const char* src = (const char*)(x + node * (long)ND) + pc4 * 16;
            uint32_t dst = sb + SM_ARAW + row * 512 + pc4 * 16;
            int nb = (tile < ntiles && node < nnodes) ? 16 : 0;
            if (nb == 0) src = (const char*)x;
            CP_ASYNC16(dst, src, nb);
        }
        CP_COMMIT();
    }

    // ---- build W' fp16 image while first tile loads ----
    // W'[n][k]: n<128 -> W1[k][n] ; n>=128 -> W1[128+k][n-128]
    #pragma unroll
    for (int i = tid; i < 256 * 128; i += 256) {
        int r = i >> 7, c = i & 127;
        int k = (r < 128) ? r : (r - 128);
        int n = (r < 128) ? c : (c + 128);
        __half hv = __float2half_rn(W1[i]);
        *(__half*)(smem + SM_W + SWZ((uint32_t)(n * 256 + k * 2))) = hv;
    }
    if (tid < 128) ((float*)(smem + SM_B1))[tid] = b1[tid];
    __syncthreads();

    // ldmatrix lane address components
    const int a_row = (lane & 15);
    const int a_ko  = (lane >> 4) << 4;
    const int b_row = (lane & 7) + ((lane >> 4) << 3);
    const int b_ko  = ((lane >> 3) & 1) << 4;

    for (; tile < ntiles; tile += gridDim.x) {
        const long base = (long)tile * TILE_M;

        // ---- convert raw tile -> fp16 (thread-private chunks; swizzled) ----
        CP_WAIT0();
        #pragma unroll
        for (int it = 0; it < 8; it++) {
            int row = prow + it * 8;
            float4 v = *(const float4*)(smem + SM_ARAW + row * 512 + pc4 * 16);
            __half2 h01 = __floats2half2_rn(v.x, v.y);
            __half2 h23 = __floats2half2_rn(v.z, v.w);
            uint2 hp; hp.x = *(uint32_t*)&h01; hp.y = *(uint32_t*)&h23;
            *(uint2*)(smem + SM_AH + SWZ((uint32_t)(row * 256 + pc4 * 8))) = hp;
        }
        __syncthreads();   // AH ready; all done reading ARAW

        // ---- cp.async next tile into ARAW (overlaps MMA) ----
        {
            int nxt = tile + gridDim.x;
            long nbase = (long)nxt * TILE_M;
            #pragma unroll
            for (int it = 0; it < 8; it++) {
                int row = prow + it * 8;
                long node = nbase + row;
                const char* src = (const char*)(x + node * (long)ND) + pc4 * 16;
                uint32_t dst = sb + SM_ARAW + row * 512 + pc4 * 16;
                int nb = (nxt < ntiles && node < nnodes) ? 16 : 0;
                if (nb == 0) src = (const char*)x;
                CP_ASYNC16(dst, src, nb);
            }
            CP_COMMIT();
        }

        // ---- compute: acc[2 ms][8 ns][4] ----
        float acc[2][8][4];
        #pragma unroll
        for (int ms = 0; ms < 2; ms++)
            #pragma unroll
            for (int ns = 0; ns < 8; ns++)
                #pragma unroll
                for (int e = 0; e < 4; e++) acc[ms][ns][e] = 0.f;

        #pragma unroll
        for (int ks = 0; ks < 8; ks++) {
            uint32_t av[2][4], bv[16];
            #pragma unroll
            for (int ms = 0; ms < 2; ms++) {
                uint32_t ab = SWZ((uint32_t)((warp_m * 32 + ms * 16 + a_row) * 256
                                             + ks * 32 + a_ko));
                LDSM4(av[ms], sb + SM_AH + ab);
            }
            #pragma unroll
            for (int bj = 0; bj < 4; bj++) {
                uint32_t bb = SWZ((uint32_t)((warp_n * 64 + bj * 16 + b_row) * 256
                                             + ks * 32 + b_ko));
                LDSM4(&bv[bj * 4], sb + SM_W + bb);
            }
            #pragma unroll
            for (int ms = 0; ms < 2; ms++)
                #pragma unroll
                for (int ns = 0; ns < 8; ns++)
                    MMA16816F(acc[ms][ns], av[ms], &bv[ns * 2]);
        }

        // ---- epilogue: fp16 stores ----
        __half* dsth = (warp_n < 2) ? g_Ah : g_Bh;
        const int colbase = (warp_n & 1) * 64 + 2 * (lane & 3);
        const int rowbase = warp_m * 32 + (lane >> 2);
        const float* b1s = (const float*)(smem + SM_B1);

        #pragma unroll
        for (int ms = 0; ms < 2; ms++) {
            #pragma unroll
            for (int ns = 0; ns < 8; ns++) {
                const int col = colbase + ns * 8;
                float bias0 = 0.f, bias1 = 0.f;
                if (warp_n < 2) { bias0 = b1s[col]; bias1 = b1s[col + 1]; }
                long node0 = base + rowbase + ms * 16;
                if (node0 < nnodes)
                    *(__half2*)(dsth + node0 * (long)ND + col) =
                        __floats2half2_rn(acc[ms][ns][0] + bias0, acc[ms][ns][1] + bias1);
                long node1 = node0 + 8;
                if (node1 < nnodes)
                    *(__half2*)(dsth + node1 * (long)ND + col) =
                        __floats2half2_rn(acc[ms][ns][2] + bias0, acc[ms][ns][3] + bias1);
            }
        }

        __syncthreads();   // AH reads complete before next convert overwrites
    }
}

// ---------------------------------------------------------------------------
// Stage 2 (round-9 proven config): 4 lanes/edge, 8 edges/warp, fp16 rows.
// Lane t reads chunk i*4+t -> 64 contiguous bytes per instruction, MLP=8.
// ---------------------------------------------------------------------------
__global__ __launch_bounds__(256) void edge_kernel(
    const int* __restrict__ ei,        // [2, E] int32
    const float* __restrict__ W2,      // [128, 2]
    const float* __restrict__ b2,      // [2]
    float* __restrict__ out,           // [E, 2]
    int E)
{
    __shared__ float w2a[ND];
    __shared__ float w2b[ND];
    const int tid = threadIdx.x;
    if (tid < ND) {
        w2a[tid] = W2[tid * 2 + 0];
        w2b[tid] = W2[tid * 2 + 1];
    }
    __syncthreads();

    const int lane = tid & 31;
    const int t    = lane & 3;
    const int sub  = lane >> 2;
    const float b20 = __ldg(b2), b21 = __ldg(b2 + 1);
    const __half2 z2 = __float2half2_rn(0.f);

    const int warp   = (blockIdx.x * blockDim.x + tid) >> 5;
    const int nwarps = (gridDim.x * blockDim.x) >> 5;

    const float4* wa4 = (const float4*)w2a;
    const float4* wb4 = (const float4*)w2b;

    for (int eb = warp * 8; eb < E; eb += nwarps * 8) {
        const int e = eb + sub;       // E % 8 == 0
        const int r = __ldg(ei + e);
        const int c = __ldg(ei + (size_t)E + e);

        const uint4* pa = (const uint4*)(g_Ah + (size_t)r * ND);
        const uint4* pb = (const uint4*)(g_Bh + (size_t)c * ND);

        float o0 = 0.f, o1 = 0.f;
        #pragma unroll
        for (int i = 0; i < 4; i++) {
            const int ch = i * 4 + t;              // contiguous across 4 lanes
            uint4 a4 = __ldg(pa + ch);
            uint4 b4 = __ldg(pb + ch);
            const float4 walo = wa4[ch * 2], wahi = wa4[ch * 2 + 1];
            const float4 wblo = wb4[ch * 2], wbhi = wb4[ch * 2 + 1];

            const __half2* ap = (const __half2*)&a4;
            const __half2* bp = (const __half2*)&b4;

            float2 f0 = __half22float2(__hmax2(__hadd2(ap[0], bp[0]), z2));
            float2 f1 = __half22float2(__hmax2(__hadd2(ap[1], bp[1]), z2));
            float2 f2 = __half22float2(__hmax2(__hadd2(ap[2], bp[2]), z2));
            float2 f3 = __half22float2(__hmax2(__hadd2(ap[3], bp[3]), z2));

            o0 = fmaf(f0.x, walo.x, fmaf(f0.y, walo.y, o0));
            o0 = fmaf(f1.x, walo.z, fmaf(f1.y, walo.w, o0));
            o0 = fmaf(f2.x, wahi.x, fmaf(f2.y, wahi.y, o0));
            o0 = fmaf(f3.x, wahi.z, fmaf(f3.y, wahi.w, o0));

            o1 = fmaf(f0.x, wblo.x, fmaf(f0.y, wblo.y, o1));
            o1 = fmaf(f1.x, wblo.z, fmaf(f1.y, wblo.w, o1));
            o1 = fmaf(f2.x, wbhi.x, fmaf(f2.y, wbhi.y, o1));
            o1 = fmaf(f3.x, wbhi.z, fmaf(f3.y, wbhi.w, o1));
        }

        o0 += __shfl_xor_sync(0xFFFFFFFFu, o0, 1);
        o0 += __shfl_xor_sync(0xFFFFFFFFu, o0, 2);
        o1 += __shfl_xor_sync(0xFFFFFFFFu, o1, 1);
        o1 += __shfl_xor_sync(0xFFFFFFFFu, o1, 2);

        if (t == 0) {
            *(float2*)(out + 2 * (size_t)e) = make_float2(o0 + b20, o1 + b21);
        }
    }
}

// ---------------------------------------------------------------------------
extern "C" void kernel_launch(void* const* d_in, const int* in_sizes, int n_in,
                              void* d_out, int out_size)
{
    const float* x  = (const float*)d_in[0];      // [N,128]
    const int*   ei = (const int*)d_in[1];        // [2,E] int32
    const float* W1 = (const float*)d_in[2];      // [256,128]
    const float* b1 = (const float*)d_in[3];      // [128]
    const float* W2 = (const float*)d_in[4];      // [128,2]
    const float* b2 = (const float*)d_in[5];      // [2]
    float*       out = (float*)d_out;             // [E,2]

    const int nnodes = in_sizes[0] / ND;
    const int E      = in_sizes[1] / 2;
    const int ntiles = (nnodes + TILE_M - 1) / TILE_M;

    cudaFuncSetAttribute(gemm_kernel, cudaFuncAttributeMaxDynamicSharedMemorySize,
                         SMEM_TOTAL);

    gemm_kernel<<<296, 256, SMEM_TOTAL>>>(x, W1, b1, nnodes, ntiles);
    edge_kernel<<<(E + 63) / 64, 256>>>(ei, W2, b2, out, E);
}

// round 12
// speedup vs baseline: 1.3329x; 1.1409x over previous
#include <cuda_runtime.h>
#include <cuda_bf16.h>
#include <cuda_fp16.h>
#include <cstdint>

// EdgePredictor, factorized:
//   Stage 1: fp16 1-pass GEMM  Y[100000,256] = X@W  (fp32 acc) — round-9 config,
//            measured AT the legacy-HMMA roofline (~164 TF/s). Do not touch.
//   Stage 2: out[e] = relu(A[row] + B[col]) @ W2 + b2, 4 lanes/edge, 8 edges/warp,
//            64B/instr gathers (MLP=8 proven best); W2 held as fp16 in SMEM so
//            each chunk's weights are ONE LDS.128 (in-loop LSU ops 6 -> 4).

#define ND  128
#define MAX_NODES 100000
#define TILE_M 128

__device__ __half g_Ah[(size_t)MAX_NODES * ND];   // 25.6 MB
__device__ __half g_Bh[(size_t)MAX_NODES * ND];   // 25.6 MB

// SMEM layout (dynamic, 160.5 KB)
#define SM_W    0          // 65536  W' fp16 [n=256][k=128], 256B rows, swizzled
#define SM_ARAW 65536      // 65536  raw fp32 X tile (128 x 128 f32)
#define SM_AH   131072     // 32768  fp16 X tile (128 x 128), swizzled
#define SM_B1   163840     // 512
#define SMEM_TOTAL 164352

// XOR swizzle for 256-byte rows: byte bits [4:6] ^= row bits [8:10]
#define SWZ(x) ((x) ^ (((x) >> 4) & 0x70))

static __device__ __forceinline__ uint32_t smem_u32(const void* p) {
    uint32_t a;
    asm("{ .reg .u64 t; cvta.to.shared.u64 t, %1; cvt.u32.u64 %0, t; }" : "=r"(a) : "l"(p));
    return a;
}

#define LDSM4(r, addr)                                                          \
    asm volatile("ldmatrix.sync.aligned.m8n8.x4.shared.b16 {%0,%1,%2,%3}, [%4];"\
        : "=r"((r)[0]), "=r"((r)[1]), "=r"((r)[2]), "=r"((r)[3]) : "r"(addr))

#define MMA16816F(d, a, b)                                                      \
    asm volatile("mma.sync.aligned.m16n8k16.row.col.f32.f16.f16.f32 "           \
        "{%0,%1,%2,%3}, {%4,%5,%6,%7}, {%8,%9}, {%0,%1,%2,%3};"                 \
        : "+f"((d)[0]), "+f"((d)[1]), "+f"((d)[2]), "+f"((d)[3])                \
        : "r"((a)[0]), "r"((a)[1]), "r"((a)[2]), "r"((a)[3]),                   \
          "r"((b)[0]), "r"((b)[1]))

#define CP_ASYNC16(dst, src, nbytes)                                            \
    asm volatile("cp.async.cg.shared.global [%0], [%1], 16, %2;"                \
        :: "r"(dst), "l"(src), "r"(nbytes))
#define CP_COMMIT() asm volatile("cp.async.commit_group;" ::: "memory")
#define CP_WAIT0()  asm volatile("cp.async.wait_group 0;" ::: "memory")

// ---------------------------------------------------------------------------
// Stage 1: persistent pipelined fp16 GEMM (round-9, at HMMA roofline).
// 512 threads, 16 warps (4m x 4n), CTA tile 128x256, warp tile 32x64.
// ---------------------------------------------------------------------------
__global__ __launch_bounds__(512, 1) void gemm_kernel(
    const float* __restrict__ x, const float* __restrict__ W1,
    const float* __restrict__ b1, int nnodes, int ntiles)
{
    extern __shared__ char smem[];
    const uint32_t sb = smem_u32(smem);
    const int tid  = threadIdx.x;
    const int lane = tid & 31;
    const int w    = tid >> 5;
    const int warp_m = w & 3;    // 4 groups of 32 rows
    const int warp_n = w >> 2;   // 4 groups of 64 cols

    // staging coords: 4096 float4 / 512 threads = 8 each
    const int prow = tid >> 5;          // + it*16
    const int pc4  = tid & 31;

    // ---- prefetch first tile ----
    int tile = blockIdx.x;
    {
        long base = (long)tile * TILE_M;
        #pragma unroll
        for (int it = 0; it < 8; it++) {
            int row = prow + it * 16;
            long node = base + row;
            const char* src = (const char*)(x + node * (long)ND) + pc4 * 16;
            uint32_t dst = sb + SM_ARAW + row * 512 + pc4 * 16;
            int nb = (tile < ntiles && node < nnodes) ? 16 : 0;
            if (nb == 0) src = (const char*)x;
            CP_ASYNC16(dst, src, nb);
        }
        CP_COMMIT();
    }

    // ---- prologue: build W' fp16 image while first tile loads ----
    // W'[n][k]: n<128 -> W1[k][n] ; n>=128 -> W1[128+k][n-128]
    #pragma unroll
    for (int i = tid; i < 256 * 128; i += 512) {     // coalesced read of W1
        int r = i >> 7, c = i & 127;
        int k = (r < 128) ? r : (r - 128);
        int n = (r < 128) ? c : (c + 128);
        __half hv = __float2half_rn(W1[i]);
        *(__half*)(smem + SM_W + SWZ((uint32_t)(n * 256 + k * 2))) = hv;
    }
    if (tid < 128) ((float*)(smem + SM_B1))[tid] = b1[tid];

    CP_WAIT0();
    __syncthreads();

    // ldmatrix lane address components
    const int a_row = (lane & 15);
    const int a_ko  = (lane >> 4) << 4;
    const int b_row = (lane & 7) + ((lane >> 4) << 3);
    const int b_ko  = ((lane >> 3) & 1) << 4;

    for (; tile < ntiles; tile += gridDim.x) {
        const long base = (long)tile * TILE_M;

        // ---- convert raw tile -> fp16 (swizzled) ----
        #pragma unroll
        for (int it = 0; it < 8; it++) {
            int row = prow + it * 16;
            float4 v = *(const float4*)(smem + SM_ARAW + row * 512 + pc4 * 16);
            __half2 h01 = __floats2half2_rn(v.x, v.y);
            __half2 h23 = __floats2half2_rn(v.z, v.w);
            uint2 hp;
            hp.x = *(uint32_t*)&h01; hp.y = *(uint32_t*)&h23;
            *(uint2*)(smem + SM_AH + SWZ((uint32_t)(row * 256 + pc4 * 8))) = hp;
        }
        __syncthreads();   // AH ready; all done reading ARAW

        // ---- cp.async next tile into ARAW (overlaps MMA) ----
        {
            int nxt = tile + gridDim.x;
            long nbase = (long)nxt * TILE_M;
            #pragma unroll
            for (int it = 0; it < 8; it++) {
                int row = prow + it * 16;
                long node = nbase + row;
                const char* src = (const char*)(x + node * (long)ND) + pc4 * 16;
                uint32_t dst = sb + SM_ARAW + row * 512 + pc4 * 16;
                int nb = (nxt < ntiles && node < nnodes) ? 16 : 0;
                if (nb == 0) src = (const char*)x;
                CP_ASYNC16(dst, src, nb);
            }
            CP_COMMIT();
        }

        // ---- compute: acc[2 ms][8 ns][4] ----
        float acc[2][8][4];
        #pragma unroll
        for (int ms = 0; ms < 2; ms++)
            #pragma unroll
            for (int ns = 0; ns < 8; ns++)
                #pragma unroll
                for (int e = 0; e < 4; e++) acc[ms][ns][e] = 0.f;

        #pragma unroll
        for (int ks = 0; ks < 8; ks++) {
            uint32_t av[2][4], bv[16];
            #pragma unroll
            for (int ms = 0; ms < 2; ms++) {
                uint32_t ab = SWZ((uint32_t)((warp_m * 32 + ms * 16 + a_row) * 256
                                             + ks * 32 + a_ko));
                LDSM4(av[ms], sb + SM_AH + ab);
            }
            #pragma unroll
            for (int bj = 0; bj < 4; bj++) {
                uint32_t bb = SWZ((uint32_t)((warp_n * 64 + bj * 16 + b_row) * 256
                                             + ks * 32 + b_ko));
                LDSM4(&bv[bj * 4], sb + SM_W + bb);
            }
            #pragma unroll
            for (int ms = 0; ms < 2; ms++)
                #pragma unroll
                for (int ns = 0; ns < 8; ns++)
                    MMA16816F(acc[ms][ns], av[ms], &bv[ns * 2]);
        }

        // ---- epilogue: fp16 stores ----
        __half* dsth = (warp_n < 2) ? g_Ah : g_Bh;
        const int colbase = (warp_n & 1) * 64 + 2 * (lane & 3);
        const int rowbase = warp_m * 32 + (lane >> 2);
        const float* b1s = (const float*)(smem + SM_B1);

        #pragma unroll
        for (int ms = 0; ms < 2; ms++) {
            #pragma unroll
            for (int ns = 0; ns < 8; ns++) {
                const int col = colbase + ns * 8;
                float bias0 = 0.f, bias1 = 0.f;
                if (warp_n < 2) { bias0 = b1s[col]; bias1 = b1s[col + 1]; }
                long node0 = base + rowbase + ms * 16;
                if (node0 < nnodes)
                    *(__half2*)(dsth + node0 * (long)ND + col) =
                        __floats2half2_rn(acc[ms][ns][0] + bias0, acc[ms][ns][1] + bias1);
                long node1 = node0 + 8;
                if (node1 < nnodes)
                    *(__half2*)(dsth + node1 * (long)ND + col) =
                        __floats2half2_rn(acc[ms][ns][2] + bias0, acc[ms][ns][3] + bias1);
            }
        }

        CP_WAIT0();
        __syncthreads();
    }
}

// ---------------------------------------------------------------------------
// Stage 2: 4 lanes/edge, 8 edges/warp, fp16 rows (256 B). Lane t reads chunk
// i*4+t -> 64 contiguous bytes/instr, MLP=8. W2 as fp16 in SMEM: one LDS.128
// per (chunk, class) instead of two -> in-loop LSU ops 6 -> 4 per iter.
// ---------------------------------------------------------------------------
__global__ __launch_bounds__(256) void edge_kernel(
    const int* __restrict__ ei,        // [2, E] int32
    const float* __restrict__ W2,      // [128, 2]
    const float* __restrict__ b2,      // [2]
    float* __restrict__ out,           // [E, 2]
    int E)
{
    __shared__ __half wa_h[ND];        // class-0 weights, fp16
    __shared__ __half wb_h[ND];        // class-1 weights, fp16
    const int tid = threadIdx.x;
    if (tid < ND) {
        wa_h[tid] = __float2half_rn(W2[tid * 2 + 0]);
        wb_h[tid] = __float2half_rn(W2[tid * 2 + 1]);
    }
    __syncthreads();

    const int lane = tid & 31;
    const int t    = lane & 3;
    const int sub  = lane >> 2;
    const float b20 = __ldg(b2), b21 = __ldg(b2 + 1);
    const __half2 z2 = __float2half2_rn(0.f);

    const int warp   = (blockIdx.x * blockDim.x + tid) >> 5;
    const int nwarps = (gridDim.x * blockDim.x) >> 5;

    const uint4* wa4 = (const uint4*)wa_h;   // 16 chunks x 8 half
    const uint4* wb4 = (const uint4*)wb_h;

    for (int eb = warp * 8; eb < E; eb += nwarps * 8) {
        const int e = eb + sub;       // E % 8 == 0
        const int r = __ldg(ei + e);
        const int c = __ldg(ei + (size_t)E + e);

        const uint4* pa = (const uint4*)(g_Ah + (size_t)r * ND);
        const uint4* pb = (const uint4*)(g_Bh + (size_t)c * ND);

        float o0 = 0.f, o1 = 0.f;
        #pragma unroll
        for (int i = 0; i < 4; i++) {
            const int ch = i * 4 + t;              // contiguous across 4 lanes
            uint4 a4 = __ldg(pa + ch);
            uint4 b4 = __ldg(pb + ch);
            uint4 wav = wa4[ch];                   // 8 fp16 weights, 1 LDS.128
            uint4 wbv = wb4[ch];

            const __half2* ap = (const __half2*)&a4;
            const __half2* bp = (const __half2*)&b4;
            const __half2* wap = (const __half2*)&wav;
            const __half2* wbp = (const __half2*)&wbv;

            #pragma unroll
            for (int q = 0; q < 4; q++) {
                float2 f  = __half22float2(__hmax2(__hadd2(ap[q], bp[q]), z2));
                float2 wa = __half22float2(wap[q]);
                float2 wb = __half22float2(wbp[q]);
                o0 = fmaf(f.x, wa.x, fmaf(f.y, wa.y, o0));
                o1 = fmaf(f.x, wb.x, fmaf(f.y, wb.y, o1));
            }
        }

        o0 += __shfl_xor_sync(0xFFFFFFFFu, o0, 1);
        o0 += __shfl_xor_sync(0xFFFFFFFFu, o0, 2);
        o1 += __shfl_xor_sync(0xFFFFFFFFu, o1, 1);
        o1 += __shfl_xor_sync(0xFFFFFFFFu, o1, 2);

        if (t == 0) {
            *(float2*)(out + 2 * (size_t)e) = make_float2(o0 + b20, o1 + b21);
        }
    }
}

// ---------------------------------------------------------------------------
extern "C" void kernel_launch(void* const* d_in, const int* in_sizes, int n_in,
                              void* d_out, int out_size)
{
    const float* x  = (const float*)d_in[0];      // [N,128]
    const int*   ei = (const int*)d_in[1];        // [2,E] int32
    const float* W1 = (const float*)d_in[2];      // [256,128]
    const float* b1 = (const float*)d_in[3];      // [128]
    const float* W2 = (const float*)d_in[4];      // [128,2]
    const float* b2 = (const float*)d_in[5];      // [2]
    float*       out = (float*)d_out;             // [E,2]

    const int nnodes = in_sizes[0] / ND;
    const int E      = in_sizes[1] / 2;
    const int ntiles = (nnodes + TILE_M - 1) / TILE_M;

    cudaFuncSetAttribute(gemm_kernel, cudaFuncAttributeMaxDynamicSharedMemorySize,
                         SMEM_TOTAL);

    gemm_kernel<<<148, 512, SMEM_TOTAL>>>(x, W1, b1, nnodes, ntiles);
    edge_kernel<<<(E + 63) / 64, 256>>>(ei, W2, b2, out, E);
}

// round 13
// speedup vs baseline: 1.4003x; 1.0505x over previous
#include <cuda_runtime.h>
#include <cuda_bf16.h>
#include <cuda_fp16.h>
#include <cstdint>

// EdgePredictor, factorized:
//   Stage 1: fp16 1-pass GEMM  Y[100000,256] = X@W  (fp32 acc) — round-9 config,
//            measured AT the legacy-HMMA roofline (~164 TF/s). Unchanged.
//   Stage 2: out[e] = relu(A[row] + B[col]) @ W2 + b2, 4 lanes/edge, fp16 W2 in
//            SMEM; TWO 8-edge groups in flight per warp (MLP 8 -> 16 LDG.128).

#define ND  128
#define MAX_NODES 100000
#define TILE_M 128

__device__ __half g_Ah[(size_t)MAX_NODES * ND];   // 25.6 MB
__device__ __half g_Bh[(size_t)MAX_NODES * ND];   // 25.6 MB

// SMEM layout (dynamic, 160.5 KB)
#define SM_W    0          // 65536  W' fp16 [n=256][k=128], 256B rows, swizzled
#define SM_ARAW 65536      // 65536  raw fp32 X tile (128 x 128 f32)
#define SM_AH   131072     // 32768  fp16 X tile (128 x 128), swizzled
#define SM_B1   163840     // 512
#define SMEM_TOTAL 164352

// XOR swizzle for 256-byte rows: byte bits [4:6] ^= row bits [8:10]
#define SWZ(x) ((x) ^ (((x) >> 4) & 0x70))

static __device__ __forceinline__ uint32_t smem_u32(const void* p) {
    uint32_t a;
    asm("{ .reg .u64 t; cvta.to.shared.u64 t, %1; cvt.u32.u64 %0, t; }" : "=r"(a) : "l"(p));
    return a;
}

#define LDSM4(r, addr)                                                          \
    asm volatile("ldmatrix.sync.aligned.m8n8.x4.shared.b16 {%0,%1,%2,%3}, [%4];"\
        : "=r"((r)[0]), "=r"((r)[1]), "=r"((r)[2]), "=r"((r)[3]) : "r"(addr))

#define MMA16816F(d, a, b)                                                      \
    asm volatile("mma.sync.aligned.m16n8k16.row.col.f32.f16.f16.f32 "           \
        "{%0,%1,%2,%3}, {%4,%5,%6,%7}, {%8,%9}, {%0,%1,%2,%3};"                 \
        : "+f"((d)[0]), "+f"((d)[1]), "+f"((d)[2]), "+f"((d)[3])                \
        : "r"((a)[0]), "r"((a)[1]), "r"((a)[2]), "r"((a)[3]),                   \
          "r"((b)[0]), "r"((b)[1]))

#define CP_ASYNC16(dst, src, nbytes)                                            \
    asm volatile("cp.async.cg.shared.global [%0], [%1], 16, %2;"                \
        :: "r"(dst), "l"(src), "r"(nbytes))
#define CP_COMMIT() asm volatile("cp.async.commit_group;" ::: "memory")
#define CP_WAIT0()  asm volatile("cp.async.wait_group 0;" ::: "memory")

// ---------------------------------------------------------------------------
// Stage 1: persistent pipelined fp16 GEMM (at HMMA roofline — unchanged).
// 512 threads, 16 warps (4m x 4n), CTA tile 128x256, warp tile 32x64.
// ---------------------------------------------------------------------------
__global__ __launch_bounds__(512, 1) void gemm_kernel(
    const float* __restrict__ x, const float* __restrict__ W1,
    const float* __restrict__ b1, int nnodes, int ntiles)
{
    extern __shared__ char smem[];
    const uint32_t sb = smem_u32(smem);
    const int tid  = threadIdx.x;
    const int lane = tid & 31;
    const int w    = tid >> 5;
    const int warp_m = w & 3;
    const int warp_n = w >> 2;

    const int prow = tid >> 5;
    const int pc4  = tid & 31;

    int tile = blockIdx.x;
    {
        long base = (long)tile * TILE_M;
        #pragma unroll
        for (int it = 0; it < 8; it++) {
            int row = prow + it * 16;
            long node = base + row;
            const char* src = (const char*)(x + node * (long)ND) + pc4 * 16;
            uint32_t dst = sb + SM_ARAW + row * 512 + pc4 * 16;
            int nb = (tile < ntiles && node < nnodes) ? 16 : 0;
            if (nb == 0) src = (const char*)x;
            CP_ASYNC16(dst, src, nb);
        }
        CP_COMMIT();
    }

    // W'[n][k]: n<128 -> W1[k][n] ; n>=128 -> W1[128+k][n-128]
    #pragma unroll
    for (int i = tid; i < 256 * 128; i += 512) {
        int r = i >> 7, c = i & 127;
        int k = (r < 128) ? r : (r - 128);
        int n = (r < 128) ? c : (c + 128);
        __half hv = __float2half_rn(W1[i]);
        *(__half*)(smem + SM_W + SWZ((uint32_t)(n * 256 + k * 2))) = hv;
    }
    if (tid < 128) ((float*)(smem + SM_B1))[tid] = b1[tid];

    CP_WAIT0();
    __syncthreads();

    const int a_row = (lane & 15);
    const int a_ko  = (lane >> 4) << 4;
    const int b_row = (lane & 7) + ((lane >> 4) << 3);
    const int b_ko  = ((lane >> 3) & 1) << 4;

    for (; tile < ntiles; tile += gridDim.x) {
        const long base = (long)tile * TILE_M;

        #pragma unroll
        for (int it = 0; it < 8; it++) {
            int row = prow + it * 16;
            float4 v = *(const float4*)(smem + SM_ARAW + row * 512 + pc4 * 16);
            __half2 h01 = __floats2half2_rn(v.x, v.y);
            __half2 h23 = __floats2half2_rn(v.z, v.w);
            uint2 hp;
            hp.x = *(uint32_t*)&h01; hp.y = *(uint32_t*)&h23;
            *(uint2*)(smem + SM_AH + SWZ((uint32_t)(row * 256 + pc4 * 8))) = hp;
        }
        __syncthreads();

        {
            int nxt = tile + gridDim.x;
            long nbase = (long)nxt * TILE_M;
            #pragma unroll
            for (int it = 0; it < 8; it++) {
                int row = prow + it * 16;
                long node = nbase + row;
                const char* src = (const char*)(x + node * (long)ND) + pc4 * 16;
                uint32_t dst = sb + SM_ARAW + row * 512 + pc4 * 16;
                int nb = (nxt < ntiles && node < nnodes) ? 16 : 0;
                if (nb == 0) src = (const char*)x;
                CP_ASYNC16(dst, src, nb);
            }
            CP_COMMIT();
        }

        float acc[2][8][4];
        #pragma unroll
        for (int ms = 0; ms < 2; ms++)
            #pragma unroll
            for (int ns = 0; ns < 8; ns++)
                #pragma unroll
                for (int e = 0; e < 4; e++) acc[ms][ns][e] = 0.f;

        #pragma unroll
        for (int ks = 0; ks < 8; ks++) {
            uint32_t av[2][4], bv[16];
            #pragma unroll
            for (int ms = 0; ms < 2; ms++) {
                uint32_t ab = SWZ((uint32_t)((warp_m * 32 + ms * 16 + a_row) * 256
                                             + ks * 32 + a_ko));
                LDSM4(av[ms], sb + SM_AH + ab);
            }
            #pragma unroll
            for (int bj = 0; bj < 4; bj++) {
                uint32_t bb = SWZ((uint32_t)((warp_n * 64 + bj * 16 + b_row) * 256
                                             + ks * 32 + b_ko));
                LDSM4(&bv[bj * 4], sb + SM_W + bb);
            }
            #pragma unroll
            for (int ms = 0; ms < 2; ms++)
                #pragma unroll
                for (int ns = 0; ns < 8; ns++)
                    MMA16816F(acc[ms][ns], av[ms], &bv[ns * 2]);
        }

        __half* dsth = (warp_n < 2) ? g_Ah : g_Bh;
        const int colbase = (warp_n & 1) * 64 + 2 * (lane & 3);
        const int rowbase = warp_m * 32 + (lane >> 2);
        const float* b1s = (const float*)(smem + SM_B1);

        #pragma unroll
        for (int ms = 0; ms < 2; ms++) {
            #pragma unroll
            for (int ns = 0; ns < 8; ns++) {
                const int col = colbase + ns * 8;
                float bias0 = 0.f, bias1 = 0.f;
                if (warp_n < 2) { bias0 = b1s[col]; bias1 = b1s[col + 1]; }
                long node0 = base + rowbase + ms * 16;
                if (node0 < nnodes)
                    *(__half2*)(dsth + node0 * (long)ND + col) =
                        __floats2half2_rn(acc[ms][ns][0] + bias0, acc[ms][ns][1] + bias1);
                long node1 = node0 + 8;
                if (node1 < nnodes)
                    *(__half2*)(dsth + node1 * (long)ND + col) =
                        __floats2half2_rn(acc[ms][ns][2] + bias0, acc[ms][ns][3] + bias1);
            }
        }

        CP_WAIT0();
        __syncthreads();
    }
}

// ---------------------------------------------------------------------------
// Stage 2: 4 lanes/edge, TWO 8-edge groups per warp iteration (16 edges).
// All 16 LDG.128 issued before consumption -> MLP=16 per lane. fp16 W2 SMEM.
// ---------------------------------------------------------------------------
__global__ __launch_bounds__(256) void edge_kernel(
    const int* __restrict__ ei,        // [2, E] int32
    const float* __restrict__ W2,      // [128, 2]
    const float* __restrict__ b2,      // [2]
    float* __restrict__ out,           // [E, 2]
    int E)
{
    __shared__ __half wa_h[ND];
    __shared__ __half wb_h[ND];
    const int tid = threadIdx.x;
    if (tid < ND) {
        wa_h[tid] = __float2half_rn(W2[tid * 2 + 0]);
        wb_h[tid] = __float2half_rn(W2[tid * 2 + 1]);
    }
    __syncthreads();

    const int lane = tid & 31;
    const int t    = lane & 3;
    const int sub  = lane >> 2;
    const float b20 = __ldg(b2), b21 = __ldg(b2 + 1);
    const __half2 z2 = __float2half2_rn(0.f);

    const int warp   = (blockIdx.x * blockDim.x + tid) >> 5;
    const int nwarps = (gridDim.x * blockDim.x) >> 5;

    const uint4* wa4 = (const uint4*)wa_h;   // 16 chunks x 8 half
    const uint4* wb4 = (const uint4*)wb_h;

    for (int eb = warp * 16; eb < E; eb += nwarps * 16) {
        const int e0 = eb + sub;           // E % 16 == 0
        const int e1 = eb + 8 + sub;
        const int r0 = __ldg(ei + e0);
        const int c0 = __ldg(ei + (size_t)E + e0);
        const int r1 = __ldg(ei + e1);
        const int c1 = __ldg(ei + (size_t)E + e1);

        const uint4* pa0 = (const uint4*)(g_Ah + (size_t)r0 * ND);
        const uint4* pb0 = (const uint4*)(g_Bh + (size_t)c0 * ND);
        const uint4* pa1 = (const uint4*)(g_Ah + (size_t)r1 * ND);
        const uint4* pb1 = (const uint4*)(g_Bh + (size_t)c1 * ND);

        uint4 A0[4], B0[4], A1[4], B1[4];
        #pragma unroll
        for (int i = 0; i < 4; i++) {
            const int ch = i * 4 + t;
            A0[i] = __ldg(pa0 + ch);
            B0[i] = __ldg(pb0 + ch);
            A1[i] = __ldg(pa1 + ch);
            B1[i] = __ldg(pb1 + ch);
        }

        float o00 = 0.f, o01 = 0.f, o10 = 0.f, o11 = 0.f;
        #pragma unroll
        for (int i = 0; i < 4; i++) {
            const int ch = i * 4 + t;
            uint4 wav = wa4[ch];
            uint4 wbv = wb4[ch];
            const __half2* wap = (const __half2*)&wav;
            const __half2* wbp = (const __half2*)&wbv;
            const __half2* a0p = (const __half2*)&A0[i];
            const __half2* b0p = (const __half2*)&B0[i];
            const __half2* a1p = (const __half2*)&A1[i];
            const __half2* b1p = (const __half2*)&B1[i];

            #pragma unroll
            for (int q = 0; q < 4; q++) {
                float2 wa = __half22float2(wap[q]);
                float2 wb = __half22float2(wbp[q]);
                float2 f0 = __half22float2(__hmax2(__hadd2(a0p[q], b0p[q]), z2));
                float2 f1 = __half22float2(__hmax2(__hadd2(a1p[q], b1p[q]), z2));
                o00 = fmaf(f0.x, wa.x, fmaf(f0.y, wa.y, o00));
                o01 = fmaf(f0.x, wb.x, fmaf(f0.y, wb.y, o01));
                o10 = fmaf(f1.x, wa.x, fmaf(f1.y, wa.y, o10));
                o11 = fmaf(f1.x, wb.x, fmaf(f1.y, wb.y, o11));
            }
        }

        o00 += __shfl_xor_sync(0xFFFFFFFFu, o00, 1);
        o00 += __shfl_xor_sync(0xFFFFFFFFu, o00, 2);
        o01 += __shfl_xor_sync(0xFFFFFFFFu, o01, 1);
        o01 += __shfl_xor_sync(0xFFFFFFFFu, o01, 2);
        o10 += __shfl_xor_sync(0xFFFFFFFFu, o10, 1);
        o10 += __shfl_xor_sync(0xFFFFFFFFu, o10, 2);
        o11 += __shfl_xor_sync(0xFFFFFFFFu, o11, 1);
        o11 += __shfl_xor_sync(0xFFFFFFFFu, o11, 2);

        if (t == 0) {
            *(float2*)(out + 2 * (size_t)e0) = make_float2(o00 + b20, o01 + b21);
            *(float2*)(out + 2 * (size_t)e1) = make_float2(o10 + b20, o11 + b21);
        }
    }
}

// ---------------------------------------------------------------------------
extern "C" void kernel_launch(void* const* d_in, const int* in_sizes, int n_in,
                              void* d_out, int out_size)
{
    const float* x  = (const float*)d_in[0];      // [N,128]
    const int*   ei = (const int*)d_in[1];        // [2,E] int32
    const float* W1 = (const float*)d_in[2];      // [256,128]
    const float* b1 = (const float*)d_in[3];      // [128]
    const float* W2 = (const float*)d_in[4];      // [128,2]
    const float* b2 = (const float*)d_in[5];      // [2]
    float*       out = (float*)d_out;             // [E,2]

    const int nnodes = in_sizes[0] / ND;
    const int E      = in_sizes[1] / 2;
    const int ntiles = (nnodes + TILE_M - 1) / TILE_M;

    cudaFuncSetAttribute(gemm_kernel, cudaFuncAttributeMaxDynamicSharedMemorySize,
                         SMEM_TOTAL);

    gemm_kernel<<<148, 512, SMEM_TOTAL>>>(x, W1, b1, nnodes, ntiles);
    edge_kernel<<<(E + 127) / 128, 256>>>(ei, W2, b2, out, E);
}

// round 14
// speedup vs baseline: 1.5320x; 1.0941x over previous
#include <cuda_runtime.h>
#include <cuda_bf16.h>
#include <cuda_fp16.h>
#include <cstdint>

// EdgePredictor, factorized:
//   Stage 1: fp16 1-pass GEMM  Y[100000,256] = X@W  (fp32 acc), TILE_M=64 for
//            load balance (1563 tiles / 148 CTAs -> 4% imbalance, was 14%).
//   Stage 2: out[e] = relu(A[row] + B[col]) @ W2 + b2, 4 lanes/edge, fp16 W2,
//            two 8-edge groups in flight (MLP=16); 128-thread blocks for
//            occupancy granularity (9 blocks/SM at 54 regs).

#define ND  128
#define MAX_NODES 100000
#define TILE_M 64

__device__ __half g_Ah[(size_t)MAX_NODES * ND];   // 25.6 MB
__device__ __half g_Bh[(size_t)MAX_NODES * ND];   // 25.6 MB

// SMEM layout (dynamic, 112.8 KB)
#define SM_W    0          // 65536  W' fp16 [n=256][k=128], 256B rows, swizzled
#define SM_ARAW 65536      // 32768  raw fp32 X tile (64 x 128 f32)
#define SM_AH   98304      // 16384  fp16 X tile (64 x 128), swizzled
#define SM_B1   114688     // 512
#define SMEM_TOTAL 115200

// XOR swizzle for 256-byte rows: byte bits [4:6] ^= row bits [8:10]
#define SWZ(x) ((x) ^ (((x) >> 4) & 0x70))

static __device__ __forceinline__ uint32_t smem_u32(const void* p) {
    uint32_t a;
    asm("{ .reg .u64 t; cvta.to.shared.u64 t, %1; cvt.u32.u64 %0, t; }" : "=r"(a) : "l"(p));
    return a;
}

#define LDSM4(r, addr)                                                          \
    asm volatile("ldmatrix.sync.aligned.m8n8.x4.shared.b16 {%0,%1,%2,%3}, [%4];"\
        : "=r"((r)[0]), "=r"((r)[1]), "=r"((r)[2]), "=r"((r)[3]) : "r"(addr))

#define MMA16816F(d, a, b)                                                      \
    asm volatile("mma.sync.aligned.m16n8k16.row.col.f32.f16.f16.f32 "           \
        "{%0,%1,%2,%3}, {%4,%5,%6,%7}, {%8,%9}, {%0,%1,%2,%3};"                 \
        : "+f"((d)[0]), "+f"((d)[1]), "+f"((d)[2]), "+f"((d)[3])                \
        : "r"((a)[0]), "r"((a)[1]), "r"((a)[2]), "r"((a)[3]),                   \
          "r"((b)[0]), "r"((b)[1]))

#define CP_ASYNC16(dst, src, nbytes)                                            \
    asm volatile("cp.async.cg.shared.global [%0], [%1], 16, %2;"                \
        :: "r"(dst), "l"(src), "r"(nbytes))
#define CP_COMMIT() asm volatile("cp.async.commit_group;" ::: "memory")
#define CP_WAIT0()  asm volatile("cp.async.wait_group 0;" ::: "memory")

// ---------------------------------------------------------------------------
// Stage 1: persistent pipelined fp16 GEMM. 512 threads, 16 warps (2m x 8n),
// CTA tile 64x256, warp tile 32x32.
// ---------------------------------------------------------------------------
__global__ __launch_bounds__(512, 1) void gemm_kernel(
    const float* __restrict__ x, const float* __restrict__ W1,
    const float* __restrict__ b1, int nnodes, int ntiles)
{
    extern __shared__ char smem[];
    const uint32_t sb = smem_u32(smem);
    const int tid  = threadIdx.x;
    const int lane = tid & 31;
    const int w    = tid >> 5;
    const int warp_m = w & 1;    // 2 groups of 32 rows
    const int warp_n = w >> 1;   // 8 groups of 32 cols

    // staging coords: 2048 float4 / 512 threads = 4 each
    const int prow = tid >> 5;          // + it*16
    const int pc4  = tid & 31;

    // ---- prefetch first tile ----
    int tile = blockIdx.x;
    {
        long base = (long)tile * TILE_M;
        #pragma unroll
        for (int it = 0; it < 4; it++) {
            int row = prow + it * 16;
            long node = base + row;
            const char* src = (const char*)(x + node * (long)ND) + pc4 * 16;
            uint32_t dst = sb + SM_ARAW + row * 512 + pc4 * 16;
            int nb = (tile < ntiles && node < nnodes) ? 16 : 0;
            if (nb == 0) src = (const char*)x;
            CP_ASYNC16(dst, src, nb);
        }
        CP_COMMIT();
    }

    // ---- prologue: build W' fp16 image while first tile loads ----
    // W'[n][k]: n<128 -> W1[k][n] ; n>=128 -> W1[128+k][n-128]
    #pragma unroll
    for (int i = tid; i < 256 * 128; i += 512) {     // coalesced read of W1
        int r = i >> 7, c = i & 127;
        int k = (r < 128) ? r : (r - 128);
        int n = (r < 128) ? c : (c + 128);
        __half hv = __float2half_rn(W1[i]);
        *(__half*)(smem + SM_W + SWZ((uint32_t)(n * 256 + k * 2))) = hv;
    }
    if (tid < 128) ((float*)(smem + SM_B1))[tid] = b1[tid];

    CP_WAIT0();
    __syncthreads();

    // ldmatrix lane address components
    const int a_row = (lane & 15);
    const int a_ko  = (lane >> 4) << 4;
    const int b_row = (lane & 7) + ((lane >> 4) << 3);
    const int b_ko  = ((lane >> 3) & 1) << 4;

    for (; tile < ntiles; tile += gridDim.x) {
        const long base = (long)tile * TILE_M;

        // ---- convert raw tile -> fp16 (swizzled) ----
        #pragma unroll
        for (int it = 0; it < 4; it++) {
            int row = prow + it * 16;
            float4 v = *(const float4*)(smem + SM_ARAW + row * 512 + pc4 * 16);
            __half2 h01 = __floats2half2_rn(v.x, v.y);
            __half2 h23 = __floats2half2_rn(v.z, v.w);
            uint2 hp;
            hp.x = *(uint32_t*)&h01; hp.y = *(uint32_t*)&h23;
            *(uint2*)(smem + SM_AH + SWZ((uint32_t)(row * 256 + pc4 * 8))) = hp;
        }
        __syncthreads();   // AH ready; all done reading ARAW

        // ---- cp.async next tile into ARAW (overlaps MMA) ----
        {
            int nxt = tile + gridDim.x;
            long nbase = (long)nxt * TILE_M;
            #pragma unroll
            for (int it = 0; it < 4; it++) {
                int row = prow + it * 16;
                long node = nbase + row;
                const char* src = (const char*)(x + node * (long)ND) + pc4 * 16;
                uint32_t dst = sb + SM_ARAW + row * 512 + pc4 * 16;
                int nb = (nxt < ntiles && node < nnodes) ? 16 : 0;
                if (nb == 0) src = (const char*)x;
                CP_ASYNC16(dst, src, nb);
            }
            CP_COMMIT();
        }

        // ---- compute: acc[2 ms][4 ns][4] ----
        float acc[2][4][4];
        #pragma unroll
        for (int ms = 0; ms < 2; ms++)
            #pragma unroll
            for (int ns = 0; ns < 4; ns++)
                #pragma unroll
                for (int e = 0; e < 4; e++) acc[ms][ns][e] = 0.f;

        #pragma unroll
        for (int ks = 0; ks < 8; ks++) {
            uint32_t av[2][4], bv[8];
            #pragma unroll
            for (int ms = 0; ms < 2; ms++) {
                uint32_t ab = SWZ((uint32_t)((warp_m * 32 + ms * 16 + a_row) * 256
                                             + ks * 32 + a_ko));
                LDSM4(av[ms], sb + SM_AH + ab);
            }
            #pragma unroll
            for (int bj = 0; bj < 2; bj++) {
                uint32_t bb = SWZ((uint32_t)((warp_n * 32 + bj * 16 + b_row) * 256
                                             + ks * 32 + b_ko));
                LDSM4(&bv[bj * 4], sb + SM_W + bb);
            }
            #pragma unroll
            for (int ms = 0; ms < 2; ms++)
                #pragma unroll
                for (int ns = 0; ns < 4; ns++)
                    MMA16816F(acc[ms][ns], av[ms], &bv[ns * 2]);
        }

        // ---- epilogue: fp16 stores ----
        __half* dsth = (warp_n < 4) ? g_Ah : g_Bh;
        const int colbase = (warp_n & 3) * 32 + 2 * (lane & 3);
        const int rowbase = warp_m * 32 + (lane >> 2);
        const float* b1s = (const float*)(smem + SM_B1);

        #pragma unroll
        for (int ms = 0; ms < 2; ms++) {
            #pragma unroll
            for (int ns = 0; ns < 4; ns++) {
                const int col = colbase + ns * 8;
                float bias0 = 0.f, bias1 = 0.f;
                if (warp_n < 4) { bias0 = b1s[col]; bias1 = b1s[col + 1]; }
                long node0 = base + rowbase + ms * 16;
                if (node0 < nnodes)
                    *(__half2*)(dsth + node0 * (long)ND + col) =
                        __floats2half2_rn(acc[ms][ns][0] + bias0, acc[ms][ns][1] + bias1);
                long node1 = node0 + 8;
                if (node1 < nnodes)
                    *(__half2*)(dsth + node1 * (long)ND + col) =
                        __floats2half2_rn(acc[ms][ns][2] + bias0, acc[ms][ns][3] + bias1);
            }
        }

        CP_WAIT0();
        __syncthreads();
    }
}

// ---------------------------------------------------------------------------
// Stage 2: 4 lanes/edge, TWO 8-edge groups per warp iteration (MLP=16).
// 128-thread blocks: 9 blocks/SM at 54 regs -> more resident warps.
// ---------------------------------------------------------------------------
__global__ __launch_bounds__(128) void edge_kernel(
    const int* __restrict__ ei,        // [2, E] int32
    const float* __restrict__ W2,      // [128, 2]
    const float* __restrict__ b2,      // [2]
    float* __restrict__ out,           // [E, 2]
    int E)
{
    __shared__ __half wa_h[ND];
    __shared__ __half wb_h[ND];
    const int tid = threadIdx.x;
    if (tid < ND) {
        wa_h[tid] = __float2half_rn(W2[tid * 2 + 0]);
        wb_h[tid] = __float2half_rn(W2[tid * 2 + 1]);
    }
    __syncthreads();

    const int lane = tid & 31;
    const int t    = lane & 3;
    const int sub  = lane >> 2;
    const float b20 = __ldg(b2), b21 = __ldg(b2 + 1);
    const __half2 z2 = __float2half2_rn(0.f);

    const int warp   = (blockIdx.x * blockDim.x + tid) >> 5;
    const int nwarps = (gridDim.x * blockDim.x) >> 5;

    const uint4* wa4 = (const uint4*)wa_h;   // 16 chunks x 8 half
    const uint4* wb4 = (const uint4*)wb_h;

    for (int eb = warp * 16; eb < E; eb += nwarps * 16) {
        const int e0 = eb + sub;           // E % 16 == 0
        const int e1 = eb + 8 + sub;
        const int r0 = __ldg(ei + e0);
        const int c0 = __ldg(ei + (size_t)E + e0);
        const int r1 = __ldg(ei + e1);
        const int c1 = __ldg(ei + (size_t)E + e1);

        const uint4* pa0 = (const uint4*)(g_Ah + (size_t)r0 * ND);
        const uint4* pb0 = (const uint4*)(g_Bh + (size_t)c0 * ND);
        const uint4* pa1 = (const uint4*)(g_Ah + (size_t)r1 * ND);
        const uint4* pb1 = (const uint4*)(g_Bh + (size_t)c1 * ND);

        uint4 A0[4], B0[4], A1[4], B1[4];
        #pragma unroll
        for (int i = 0; i < 4; i++) {
            const int ch = i * 4 + t;
            A0[i] = __ldg(pa0 + ch);
            B0[i] = __ldg(pb0 + ch);
            A1[i] = __ldg(pa1 + ch);
            B1[i] = __ldg(pb1 + ch);
        }

        float o00 = 0.f, o01 = 0.f, o10 = 0.f, o11 = 0.f;
        #pragma unroll
        for (int i = 0; i < 4; i++) {
            const int ch = i * 4 + t;
            uint4 wav = wa4[ch];
            uint4 wbv = wb4[ch];
            const __half2* wap = (const __half2*)&wav;
            const __half2* wbp = (const __half2*)&wbv;
            const __half2* a0p = (const __half2*)&A0[i];
            const __half2* b0p = (const __half2*)&B0[i];
            const __half2* a1p = (const __half2*)&A1[i];
            const __half2* b1p = (const __half2*)&B1[i];

            #pragma unroll
            for (int q = 0; q < 4; q++) {
                float2 wa = __half22float2(wap[q]);
                float2 wb = __half22float2(wbp[q]);
                float2 f0 = __half22float2(__hmax2(__hadd2(a0p[q], b0p[q]), z2));
                float2 f1 = __half22float2(__hmax2(__hadd2(a1p[q], b1p[q]), z2));
                o00 = fmaf(f0.x, wa.x, fmaf(f0.y, wa.y, o00));
                o01 = fmaf(f0.x, wb.x, fmaf(f0.y, wb.y, o01));
                o10 = fmaf(f1.x, wa.x, fmaf(f1.y, wa.y, o10));
                o11 = fmaf(f1.x, wb.x, fmaf(f1.y, wb.y, o11));
            }
        }

        o00 += __shfl_xor_sync(0xFFFFFFFFu, o00, 1);
        o00 += __shfl_xor_sync(0xFFFFFFFFu, o00, 2);
        o01 += __shfl_xor_sync(0xFFFFFFFFu, o01, 1);
        o01 += __shfl_xor_sync(0xFFFFFFFFu, o01, 2);
        o10 += __shfl_xor_sync(0xFFFFFFFFu, o10, 1);
        o10 += __shfl_xor_sync(0xFFFFFFFFu, o10, 2);
        o11 += __shfl_xor_sync(0xFFFFFFFFu, o11, 1);
        o11 += __shfl_xor_sync(0xFFFFFFFFu, o11, 2);

        if (t == 0) {
            *(float2*)(out + 2 * (size_t)e0) = make_float2(o00 + b20, o01 + b21);
            *(float2*)(out + 2 * (size_t)e1) = make_float2(o10 + b20, o11 + b21);
        }
    }
}

// ---------------------------------------------------------------------------
extern "C" void kernel_launch(void* const* d_in, const int* in_sizes, int n_in,
                              void* d_out, int out_size)
{
    const float* x  = (const float*)d_in[0];      // [N,128]
    const int*   ei = (const int*)d_in[1];        // [2,E] int32
    const float* W1 = (const float*)d_in[2];      // [256,128]
    const float* b1 = (const float*)d_in[3];      // [128]
    const float* W2 = (const float*)d_in[4];      // [128,2]
    const float* b2 = (const float*)d_in[5];      // [2]
    float*       out = (float*)d_out;             // [E,2]

    const int nnodes = in_sizes[0] / ND;
    const int E      = in_sizes[1] / 2;
    const int ntiles = (nnodes + TILE_M - 1) / TILE_M;

    cudaFuncSetAttribute(gemm_kernel, cudaFuncAttributeMaxDynamicSharedMemorySize,
                         SMEM_TOTAL);

    gemm_kernel<<<148, 512, SMEM_TOTAL>>>(x, W1, b1, nnodes, ntiles);
    edge_kernel<<<(E + 63) / 64, 128>>>(ei, W2, b2, out, E);
}